// round 16
// baseline (speedup 1.0000x reference)
#include <cuda_runtime.h>
#include <cuda_fp16.h>
#include <cstdint>
#include <cstddef>

// ===================== problem constants =====================
static constexpr int NB   = 8192;               // batch
static constexpr int NIN  = 1024;               // in features
static constexpr int NOUT = 1024;               // out features
static constexpr int COEF = 8;                  // grid_size + spline_order
static constexpr int NK   = NIN + NIN * COEF;   // 9216 fused K

// ===================== gemm tiling =====================
static constexpr int BM = 256;
static constexpr int BN = 128;
static constexpr int BK = 128;                  // two 64-half sub-tiles per stage
static constexpr int KT_PER_TILE = NK / BK;     // 72
static constexpr int STAGES = 2;

static constexpr uint32_t A_SUB  = (uint32_t)BM * 64 * 2;      // 32768
static constexpr uint32_t B_SUB  = (uint32_t)BN * 64 * 2;      // 16384
static constexpr uint32_t A_TILE = 2 * A_SUB;                  // 65536
static constexpr uint32_t B_TILE = 2 * B_SUB;                  // 32768
static constexpr uint32_t SMEM_TOTAL = STAGES * (A_TILE + B_TILE); // 196608

// ===================== persistent split-K schedule =====================
static constexpr int NTILES  = (NB / BM) * (NOUT / BN);        // 256 output tiles
static constexpr int TOTAL_U = NTILES * KT_PER_TILE;           // 18432 (tile,kt) units
static constexpr int NCTA    = 148;                            // 1 CTA per SM
static constexpr int U_BASE  = TOTAL_U / NCTA;                 // 124
static constexpr int U_REM   = TOTAL_U % NCTA;                 // 80 CTAs get +1

// ===================== device scratch (no allocations allowed) =====================
__device__ __align__(1024) __half g_Ah[(size_t)NB * NK];       // ~151 MB fp16 activations
__device__ __align__(1024) __half g_Wh[(size_t)NOUT * NK];     // ~19 MB fp16 packed weights
__device__ __align__(1024) float  g_part[NCTA][2][BM * BN];    // ~39 MB split-tile partials

// ===================== helpers =====================
__device__ __forceinline__ uint32_t smem_u32(const void* p) {
    uint32_t a;
    asm("{ .reg .u64 t; cvta.to.shared.u64 t, %1; cvt.u32.u64 %0, t; }" : "=r"(a) : "l"(p));
    return a;
}
__device__ __forceinline__ void cp16(uint32_t dst, const void* src) {
    asm volatile("cp.async.cg.shared.global [%0], [%1], 16;" :: "r"(dst), "l"(src) : "memory");
}
#define CP_COMMIT() asm volatile("cp.async.commit_group;" ::: "memory")
#define CP_WAIT0()  asm volatile("cp.async.wait_group 0;" ::: "memory")

// streaming (evict-first) stores for write-once data
__device__ __forceinline__ void stcs128(void* p, uint4 v) {
    asm volatile("st.global.cs.v4.u32 [%0], {%1,%2,%3,%4};"
                 :: "l"(p), "r"(v.x), "r"(v.y), "r"(v.z), "r"(v.w) : "memory");
}
__device__ __forceinline__ void stcs16(void* p, unsigned short v) {
    asm volatile("st.global.cs.u16 [%0], %1;" :: "l"(p), "h"(v) : "memory");
}

__device__ __forceinline__ void ldmx4(uint32_t& r0, uint32_t& r1, uint32_t& r2, uint32_t& r3,
                                      uint32_t addr) {
    asm volatile("ldmatrix.sync.aligned.m8n8.x4.shared.b16 {%0,%1,%2,%3}, [%4];"
                 : "=r"(r0), "=r"(r1), "=r"(r2), "=r"(r3) : "r"(addr));
}
__device__ __forceinline__ void mma16816(float& c0, float& c1, float& c2, float& c3,
                                         uint32_t a0, uint32_t a1, uint32_t a2, uint32_t a3,
                                         uint32_t b0, uint32_t b1) {
    asm volatile(
        "mma.sync.aligned.m16n8k16.row.col.f32.f16.f16.f32 "
        "{%0,%1,%2,%3}, {%4,%5,%6,%7}, {%8,%9}, {%0,%1,%2,%3};"
        : "+f"(c0), "+f"(c1), "+f"(c2), "+f"(c3)
        : "r"(a0), "r"(a1), "r"(a2), "r"(a3), "r"(b0), "r"(b1));
}

// ===================== kernel 1: prep v7 (v6 + streaming stores on g_Ah) ===============
static constexpr int WPACK_BLOCKS = (NOUT * (NK / 8)) / 256;   // 4608  (4 pairs/thread)
static constexpr int ACT_BLOCKS   = NB;                        // 8192  (1 row per block)

__global__ void kan_prep(const float* __restrict__ x,
                         const float* __restrict__ bw,
                         const float* __restrict__ sw) {
    if (blockIdx.x < WPACK_BLOCKS) {
        // ---- pack weights, 8 consecutive K-elements per thread ----
        // g_Wh[o,0:1024]=bw[o,:]; g_Wh[o,1024+i*8+g]=sw[o,i,g]
        constexpr int QK = NK / 8;                       // 1152 octets per row
        int p = blockIdx.x * blockDim.x + threadIdx.x;
        int o  = p / QK;
        int kk = (p - o * QK) * 8;                       // multiple of 8; regions align
        const float* src = (kk < NIN)
            ? bw + (size_t)o * NIN + kk
            : sw + (size_t)o * (NIN * COEF) + (kk - NIN);
        float4 f0 = *reinterpret_cast<const float4*>(src);
        float4 f1 = *reinterpret_cast<const float4*>(src + 4);
        __half2 h0 = __floats2half2_rn(f0.x, f0.y);
        __half2 h1 = __floats2half2_rn(f0.z, f0.w);
        __half2 h2 = __floats2half2_rn(f1.x, f1.y);
        __half2 h3 = __floats2half2_rn(f1.z, f1.w);
        uint4 u;
        u.x = *reinterpret_cast<uint32_t*>(&h0);
        u.y = *reinterpret_cast<uint32_t*>(&h1);
        u.z = *reinterpret_cast<uint32_t*>(&h2);
        u.w = *reinterpret_cast<uint32_t*>(&h3);
        *reinterpret_cast<uint4*>(g_Wh + (size_t)o * NK + kk) = u;
        return;
    }
    // ---- activations: one batch row per block; thread t handles inputs
    //      {t, t+256, t+512, t+768} so every spline STG.128 is lane-contiguous ----
    const int b = blockIdx.x - WPACK_BLOCKS;
    const int t = threadIdx.x;
    const float* xrow = x + (size_t)b * NIN;
    const size_t ro = (size_t)b * NK;
    __half* silu_dst = g_Ah + ro;
    __half* base_dst = g_Ah + ro + NIN;

    // batch all 4 loads up front: guaranteed MLP=4 before the compute chains
    float v[4];
#pragma unroll
    for (int e = 0; e < 4; ++e) v[e] = xrow[t + e * 256];

#pragma unroll
    for (int e = 0; e < 4; ++e) {
        const int i = t + e * 256;
        const float ve = v[e];

        // silu via fast exp + fast divide (1 MUFU.EX2 + 1 MUFU.RCP + muls)
        float s = __fdividef(ve, 1.0f + __expf(-ve));
        __half sh = __float2half_rn(s);
        stcs16(silu_dst + i, *reinterpret_cast<unsigned short*>(&sh));

        // uniform cubic B-spline bases: 4 nonzero values at slots j..j+3 of 8.
        float xs = ve * 5.0f;
        int j = __float2int_rd(xs);       // x in [0,1) -> j in [0,4]
        j = (j > 4) ? 4 : ((j < 0) ? 0 : j);
        float tt = xs - (float)j;
        float t2 = tt * tt, omt = 1.0f - tt;
        // Horner forms of the uniform cubic B-spline basis values
        float n0 = omt * omt * omt * (1.0f / 6.0f);
        float n1 = (0.5f * tt - 1.0f) * t2 + (2.0f / 3.0f);
        float n2 = ((-0.5f * tt + 0.5f) * tt + 0.5f) * tt + (1.0f / 6.0f);
        float n3 = tt * t2 * (1.0f / 6.0f);

        __half2 q01 = __floats2half2_rn(n0, n1);
        __half2 q23 = __floats2half2_rn(n2, n3);
        const uint32_t a0 = *reinterpret_cast<uint32_t*>(&q01);
        const uint32_t a1 = *reinterpret_cast<uint32_t*>(&q23);

        // branchless 128-bit shift of 64-bit packet (a1:a0) left by j*16 bits:
        //   s16 = (j&1)*16 in {0,16}; wo = j>>1 in {0,1,2} word offset.
        const uint32_t s16 = (uint32_t)(j & 1) << 4;
        const int      wo  = j >> 1;
        const uint32_t p0 = a0 << s16;
        const uint32_t p1 = __funnelshift_l(a0, a1, s16);   // s=0 -> a1
        const uint32_t p2 = s16 ? (a1 >> 16) : 0u;
        uint4 u;
        u.x = (wo == 0) ? p0 : 0u;
        u.y = (wo == 0) ? p1 : ((wo == 1) ? p0 : 0u);
        u.z = (wo == 0) ? p2 : ((wo == 1) ? p1 : p0);
        u.w = (wo == 1) ? p2 : ((wo == 2) ? p1 : 0u);
        // lane-contiguous: input i -> byte offset i*16; streaming (read-once data)
        stcs128(base_dst + (size_t)i * 8, u);
    }
}

// ===================== kernel 2: persistent split-K HMMA GEMM (unchanged) =====
__global__ void __launch_bounds__(256, 1) kan_gemm(float* __restrict__ out) {
    extern __shared__ __align__(1024) char smem[];
    const uint32_t sb = smem_u32(smem);
    const uint32_t sbA = sb;
    const uint32_t sbB = sb + STAGES * A_TILE;

    const int tid = threadIdx.x;
    const int lane = tid & 31;
    const int wid = tid >> 5;
    const int wm = wid & 3;          // 4 warps along M (64 rows each)
    const int wn = wid >> 2;         // 2 warps along N (64 cols each)

    const int c = blockIdx.x;
    const int u0 = c * U_BASE + (c < U_REM ? c : U_REM);
    const int u1 = u0 + U_BASE + (c < U_REM ? 1 : 0);

    int lt = u0 / KT_PER_TILE, lkt = u0 - lt * KT_PER_TILE;
    int ct = lt, ckt = lkt;

    auto load_stage = [&](int s, int t, int kt) {
        const int m0 = (t >> 3) * BM;
        const int n0 = (t & 7) * BN;
        const char* gA = (const char*)(g_Ah) + ((size_t)m0 * NK) * 2;
        const char* gB = (const char*)(g_Wh) + ((size_t)n0 * NK) * 2;
        const uint32_t dA = sbA + (uint32_t)s * A_TILE;
        const uint32_t dB = sbB + (uint32_t)s * B_TILE;
        const size_t koff = (size_t)kt * BK * 2;
#pragma unroll
        for (int i = 0; i < 16; ++i) {
            int cc = tid + i * 256;
            int row = cc >> 4, col = cc & 15;
            uint32_t doff = (uint32_t)(col >> 3) * A_SUB + ((uint32_t)row << 7)
                          + (((uint32_t)(col & 7) ^ (uint32_t)(row & 7)) << 4);
            cp16(dA + doff, gA + (size_t)row * (NK * 2) + koff + (size_t)col * 16);
        }
#pragma unroll
        for (int i = 0; i < 8; ++i) {
            int cc = tid + i * 256;
            int row = cc >> 4, col = cc & 15;
            uint32_t doff = (uint32_t)(col >> 3) * B_SUB + ((uint32_t)row << 7)
                          + (((uint32_t)(col & 7) ^ (uint32_t)(row & 7)) << 4);
            cp16(dB + doff, gB + (size_t)row * (NK * 2) + koff + (size_t)col * 16);
        }
    };

    load_stage(0, lt, lkt); CP_COMMIT();
    if (++lkt == KT_PER_TILE) { lkt = 0; ++lt; }

    float acc[4][8][4];
#pragma unroll
    for (int mi = 0; mi < 4; ++mi)
#pragma unroll
        for (int ni = 0; ni < 8; ++ni)
#pragma unroll
            for (int r = 0; r < 4; ++r) acc[mi][ni][r] = 0.0f;

    const int arow = wm * 64 + (lane & 15);
    const int brow = wn * 64 + (lane & 7) + ((lane >> 4) << 3);
    const uint32_t aPar  = (uint32_t)(arow & 7);
    const uint32_t bPar  = (uint32_t)(brow & 7);
    const uint32_t aKsel = (uint32_t)(lane >> 4);
    const uint32_t bKsel = (uint32_t)((lane >> 3) & 1);
    const uint32_t aBase = (uint32_t)arow << 7;
    const uint32_t bBase = (uint32_t)brow << 7;

    uint32_t fa[2][4][4];
    uint32_t fb[2][8][2];

    auto load_frags = [&](int buf, uint32_t tAs, uint32_t tBs, int ks) {
        const uint32_t aChunk = (((uint32_t)(ks * 2) + aKsel) ^ aPar) << 4;
#pragma unroll
        for (int mi = 0; mi < 4; ++mi)
            ldmx4(fa[buf][mi][0], fa[buf][mi][1], fa[buf][mi][2], fa[buf][mi][3],
                  tAs + aBase + ((uint32_t)mi << 11) + aChunk);
        const uint32_t bChunk = (((uint32_t)(ks * 2) + bKsel) ^ bPar) << 4;
#pragma unroll
        for (int g = 0; g < 4; ++g) {
            uint32_t q0, q1, q2, q3;
            ldmx4(q0, q1, q2, q3, tBs + bBase + ((uint32_t)g << 11) + bChunk);
            fb[buf][g * 2 + 0][0] = q0; fb[buf][g * 2 + 0][1] = q1;
            fb[buf][g * 2 + 1][0] = q2; fb[buf][g * 2 + 1][1] = q3;
        }
    };
    auto mma_block = [&](int buf) {
#pragma unroll
        for (int mi = 0; mi < 4; ++mi)
#pragma unroll
            for (int ni = 0; ni < 8; ++ni)
                mma16816(acc[mi][ni][0], acc[mi][ni][1], acc[mi][ni][2], acc[mi][ni][3],
                         fa[buf][mi][0], fa[buf][mi][1], fa[buf][mi][2], fa[buf][mi][3],
                         fb[buf][ni][0], fb[buf][ni][1]);
    };

    const int q = lane >> 2, p = lane & 3;
    auto dump = [&](int t, bool full) {
        if (full) {
            const int m0 = (t >> 3) * BM;
            const int n0 = (t & 7) * BN;
#pragma unroll
            for (int mi = 0; mi < 4; ++mi) {
                int mbase = m0 + wm * 64 + mi * 16 + q;
#pragma unroll
                for (int ni = 0; ni < 8; ++ni) {
                    int nbase = n0 + wn * 64 + ni * 8 + p * 2;
                    *reinterpret_cast<float2*>(out + (size_t)mbase * NOUT + nbase) =
                        make_float2(acc[mi][ni][0], acc[mi][ni][1]);
                    *reinterpret_cast<float2*>(out + (size_t)(mbase + 8) * NOUT + nbase) =
                        make_float2(acc[mi][ni][2], acc[mi][ni][3]);
                }
            }
        } else {
            const int slot = (t * KT_PER_TILE < u0) ? 0 : 1;   // head : tail
            float* pd = g_part[c][slot];
#pragma unroll
            for (int mi = 0; mi < 4; ++mi) {
                int mrel = wm * 64 + mi * 16 + q;
#pragma unroll
                for (int ni = 0; ni < 8; ++ni) {
                    int nrel = wn * 64 + ni * 8 + p * 2;
                    *reinterpret_cast<float2*>(pd + (size_t)mrel * BN + nrel) =
                        make_float2(acc[mi][ni][0], acc[mi][ni][1]);
                    *reinterpret_cast<float2*>(pd + (size_t)(mrel + 8) * BN + nrel) =
                        make_float2(acc[mi][ni][2], acc[mi][ni][3]);
                }
            }
        }
#pragma unroll
        for (int mi = 0; mi < 4; ++mi)
#pragma unroll
            for (int ni = 0; ni < 8; ++ni)
#pragma unroll
                for (int r = 0; r < 4; ++r) acc[mi][ni][r] = 0.0f;
    };

    int s = 0;
    for (int u = u0; u < u1; ++u) {
        CP_WAIT0();
        __syncthreads();

        if (u + 1 < u1) {
            load_stage(s ^ 1, lt, lkt); CP_COMMIT();
            if (++lkt == KT_PER_TILE) { lkt = 0; ++lt; }
        }

        const uint32_t tA = sbA + (uint32_t)s * A_TILE;
        const uint32_t tB = sbB + (uint32_t)s * B_TILE;

        load_frags(0, tA, tB, 0);
#pragma unroll
        for (int k8 = 0; k8 < 8; ++k8) {
            const int nk = k8 + 1;
            if (nk < 8)
                load_frags(nk & 1,
                           tA + (uint32_t)(nk >> 2) * A_SUB,
                           tB + (uint32_t)(nk >> 2) * B_SUB,
                           nk & 3);
            mma_block(k8 & 1);
        }
        s ^= 1;

        const bool tile_end  = (ckt == KT_PER_TILE - 1);
        const bool range_end = (u + 1 == u1);
        if (tile_end || range_end)
            dump(ct, tile_end && (ct * KT_PER_TILE >= u0));

        if (++ckt == KT_PER_TILE) { ckt = 0; ++ct; }
    }
}

// ===================== kernel 3: deterministic reduce of split tiles (unchanged) =======
__global__ void kan_reduce(float* __restrict__ out) {
    const int c = blockIdx.x + 1;
    const int u = c * U_BASE + (c < U_REM ? c : U_REM);
    const int kt = u % KT_PER_TILE;
    if (kt == 0) return;
    const int t = u / KT_PER_TILE;
    const int m0 = (t >> 3) * BM;
    const int n0 = (t & 7) * BN;
    const float4* pa = reinterpret_cast<const float4*>(g_part[c - 1][1]);
    const float4* pb = reinterpret_cast<const float4*>(g_part[c][0]);
    for (int i = threadIdx.x; i < (BM * BN) / 4; i += blockDim.x) {
        float4 va = pa[i], vb = pb[i];
        int e = i * 4;
        int r = e >> 7;
        int col = e & (BN - 1);
        float4 v = make_float4(va.x + vb.x, va.y + vb.y, va.z + vb.z, va.w + vb.w);
        *reinterpret_cast<float4*>(out + (size_t)(m0 + r) * NOUT + n0 + col) = v;
    }
}

// ===================== host launcher =====================
extern "C" void kernel_launch(void* const* d_in, const int* in_sizes, int n_in,
                              void* d_out, int out_size) {
    const float* x  = (const float*)d_in[0];
    const float* bw = (const float*)d_in[1];
    const float* sw = (const float*)d_in[2];
    float* out = (float*)d_out;

    cudaFuncSetAttribute(kan_gemm, cudaFuncAttributeMaxDynamicSharedMemorySize,
                         (int)SMEM_TOTAL);

    kan_prep<<<WPACK_BLOCKS + ACT_BLOCKS, 256>>>(x, bw, sw);
    kan_gemm<<<NCTA, 256, SMEM_TOTAL>>>(out);
    kan_reduce<<<NCTA - 1, 256>>>(out);
}

// round 17
// speedup vs baseline: 1.0052x; 1.0052x over previous
#include <cuda_runtime.h>
#include <cuda_fp16.h>
#include <cstdint>
#include <cstddef>

// ===================== problem constants =====================
static constexpr int NB   = 8192;               // batch
static constexpr int NIN  = 1024;               // in features
static constexpr int NOUT = 1024;               // out features
static constexpr int COEF = 8;                  // grid_size + spline_order
static constexpr int NK   = NIN + NIN * COEF;   // 9216 fused K

// ===================== gemm tiling =====================
static constexpr int BM = 256;
static constexpr int BN = 128;
static constexpr int BK = 128;                  // two 64-half sub-tiles per stage
static constexpr int KT_PER_TILE = NK / BK;     // 72
static constexpr int STAGES = 2;

static constexpr uint32_t A_SUB  = (uint32_t)BM * 64 * 2;      // 32768
static constexpr uint32_t B_SUB  = (uint32_t)BN * 64 * 2;      // 16384
static constexpr uint32_t A_TILE = 2 * A_SUB;                  // 65536
static constexpr uint32_t B_TILE = 2 * B_SUB;                  // 32768
static constexpr uint32_t SMEM_TOTAL = STAGES * (A_TILE + B_TILE); // 196608

// ===================== persistent split-K schedule =====================
static constexpr int NTILES  = (NB / BM) * (NOUT / BN);        // 256 output tiles
static constexpr int TOTAL_U = NTILES * KT_PER_TILE;           // 18432 (tile,kt) units
static constexpr int NCTA    = 148;                            // 1 CTA per SM (all co-resident)
static constexpr int U_BASE  = TOTAL_U / NCTA;                 // 124
static constexpr int U_REM   = TOTAL_U % NCTA;                 // 80 CTAs get +1

// ===================== device scratch (no allocations allowed) =====================
__device__ __align__(1024) __half g_Ah[(size_t)NB * NK];       // ~151 MB fp16 activations
__device__ __align__(1024) __half g_Wh[(size_t)NOUT * NK];     // ~19 MB fp16 packed weights
__device__ __align__(1024) float  g_part[NCTA][BM * BN];       // head partials (split tiles)
__device__ int g_flag[NCTA];                                   // head-partial-ready flags

// ===================== helpers =====================
__device__ __forceinline__ uint32_t smem_u32(const void* p) {
    uint32_t a;
    asm("{ .reg .u64 t; cvta.to.shared.u64 t, %1; cvt.u32.u64 %0, t; }" : "=r"(a) : "l"(p));
    return a;
}
__device__ __forceinline__ void cp16(uint32_t dst, const void* src) {
    asm volatile("cp.async.cg.shared.global [%0], [%1], 16;" :: "r"(dst), "l"(src) : "memory");
}
#define CP_COMMIT() asm volatile("cp.async.commit_group;" ::: "memory")
#define CP_WAIT0()  asm volatile("cp.async.wait_group 0;" ::: "memory")

__device__ __forceinline__ void ldmx4(uint32_t& r0, uint32_t& r1, uint32_t& r2, uint32_t& r3,
                                      uint32_t addr) {
    asm volatile("ldmatrix.sync.aligned.m8n8.x4.shared.b16 {%0,%1,%2,%3}, [%4];"
                 : "=r"(r0), "=r"(r1), "=r"(r2), "=r"(r3) : "r"(addr));
}
__device__ __forceinline__ void mma16816(float& c0, float& c1, float& c2, float& c3,
                                         uint32_t a0, uint32_t a1, uint32_t a2, uint32_t a3,
                                         uint32_t b0, uint32_t b1) {
    asm volatile(
        "mma.sync.aligned.m16n8k16.row.col.f32.f16.f16.f32 "
        "{%0,%1,%2,%3}, {%4,%5,%6,%7}, {%8,%9}, {%0,%1,%2,%3};"
        : "+f"(c0), "+f"(c1), "+f"(c2), "+f"(c3)
        : "r"(a0), "r"(a1), "r"(a2), "r"(a3), "r"(b0), "r"(b1));
}

// ===================== kernel 1: prep v6 (R15 best: plain stores) + flag reset =========
static constexpr int WPACK_BLOCKS = (NOUT * (NK / 8)) / 256;   // 4608  (4 pairs/thread)
static constexpr int ACT_BLOCKS   = NB;                        // 8192  (1 row per block)

__global__ void kan_prep(const float* __restrict__ x,
                         const float* __restrict__ bw,
                         const float* __restrict__ sw) {
    if (blockIdx.x < WPACK_BLOCKS) {
        // block 0 also resets the cross-CTA flags for the GEMM (stream-ordered)
        if (blockIdx.x == 0 && threadIdx.x < NCTA) g_flag[threadIdx.x] = 0;
        // ---- pack weights, 8 consecutive K-elements per thread ----
        // g_Wh[o,0:1024]=bw[o,:]; g_Wh[o,1024+i*8+g]=sw[o,i,g]
        constexpr int QK = NK / 8;                       // 1152 octets per row
        int p = blockIdx.x * blockDim.x + threadIdx.x;
        int o  = p / QK;
        int kk = (p - o * QK) * 8;                       // multiple of 8; regions align
        const float* src = (kk < NIN)
            ? bw + (size_t)o * NIN + kk
            : sw + (size_t)o * (NIN * COEF) + (kk - NIN);
        float4 f0 = *reinterpret_cast<const float4*>(src);
        float4 f1 = *reinterpret_cast<const float4*>(src + 4);
        __half2 h0 = __floats2half2_rn(f0.x, f0.y);
        __half2 h1 = __floats2half2_rn(f0.z, f0.w);
        __half2 h2 = __floats2half2_rn(f1.x, f1.y);
        __half2 h3 = __floats2half2_rn(f1.z, f1.w);
        uint4 u;
        u.x = *reinterpret_cast<uint32_t*>(&h0);
        u.y = *reinterpret_cast<uint32_t*>(&h1);
        u.z = *reinterpret_cast<uint32_t*>(&h2);
        u.w = *reinterpret_cast<uint32_t*>(&h3);
        *reinterpret_cast<uint4*>(g_Wh + (size_t)o * NK + kk) = u;
        return;
    }
    // ---- activations: one batch row per block; thread t handles inputs
    //      {t, t+256, t+512, t+768} so every spline STG.128 is lane-contiguous ----
    const int b = blockIdx.x - WPACK_BLOCKS;
    const int t = threadIdx.x;
    const float* xrow = x + (size_t)b * NIN;
    const size_t ro = (size_t)b * NK;
    __half* silu_dst = g_Ah + ro;
    __half* base_dst = g_Ah + ro + NIN;

    // batch all 4 loads up front: guaranteed MLP=4 before the compute chains
    float v[4];
#pragma unroll
    for (int e = 0; e < 4; ++e) v[e] = xrow[t + e * 256];

#pragma unroll
    for (int e = 0; e < 4; ++e) {
        const int i = t + e * 256;
        const float ve = v[e];

        // silu via fast exp + fast divide (1 MUFU.EX2 + 1 MUFU.RCP + muls)
        float s = __fdividef(ve, 1.0f + __expf(-ve));
        silu_dst[i] = __float2half_rn(s);

        // uniform cubic B-spline bases: 4 nonzero values at slots j..j+3 of 8.
        float xs = ve * 5.0f;
        int j = __float2int_rd(xs);       // x in [0,1) -> j in [0,4]
        j = (j > 4) ? 4 : ((j < 0) ? 0 : j);
        float tt = xs - (float)j;
        float t2 = tt * tt, omt = 1.0f - tt;
        // Horner forms of the uniform cubic B-spline basis values
        float n0 = omt * omt * omt * (1.0f / 6.0f);
        float n1 = (0.5f * tt - 1.0f) * t2 + (2.0f / 3.0f);
        float n2 = ((-0.5f * tt + 0.5f) * tt + 0.5f) * tt + (1.0f / 6.0f);
        float n3 = tt * t2 * (1.0f / 6.0f);

        __half2 q01 = __floats2half2_rn(n0, n1);
        __half2 q23 = __floats2half2_rn(n2, n3);
        const uint32_t a0 = *reinterpret_cast<uint32_t*>(&q01);
        const uint32_t a1 = *reinterpret_cast<uint32_t*>(&q23);

        // branchless 128-bit shift of 64-bit packet (a1:a0) left by j*16 bits
        const uint32_t s16 = (uint32_t)(j & 1) << 4;
        const int      wo  = j >> 1;
        const uint32_t p0 = a0 << s16;
        const uint32_t p1 = __funnelshift_l(a0, a1, s16);   // s=0 -> a1
        const uint32_t p2 = s16 ? (a1 >> 16) : 0u;
        uint4 u;
        u.x = (wo == 0) ? p0 : 0u;
        u.y = (wo == 0) ? p1 : ((wo == 1) ? p0 : 0u);
        u.z = (wo == 0) ? p2 : ((wo == 1) ? p1 : p0);
        u.w = (wo == 1) ? p2 : ((wo == 2) ? p1 : 0u);
        *reinterpret_cast<uint4*>(base_dst + (size_t)i * 8) = u;
    }
}

// ===================== kernel 2: persistent split-K GEMM, fused boundary merge =========
// 256x128x128 CTA tile, 64x64 warp tiles (4M x 2N), 2 smem stages, register
// double-buffered fragments. Flat (tile,kt) unit stream. Boundary-split tiles:
// the HEAD owner (CTA c) writes g_part[c][.] + raises g_flag[c]; the TAIL owner
// (CTA c-1) keeps its accumulators, spins on g_flag[c] (all 148 CTAs co-resident
// -> deadlock-free), adds the head partial, and stores the final tile itself.
__global__ void __launch_bounds__(256, 1) kan_gemm(float* __restrict__ out) {
    extern __shared__ __align__(1024) char smem[];
    const uint32_t sb = smem_u32(smem);
    const uint32_t sbA = sb;
    const uint32_t sbB = sb + STAGES * A_TILE;

    const int tid = threadIdx.x;
    const int lane = tid & 31;
    const int wid = tid >> 5;
    const int wm = wid & 3;          // 4 warps along M (64 rows each)
    const int wn = wid >> 2;         // 2 warps along N (64 cols each)

    const int c = blockIdx.x;
    const int u0 = c * U_BASE + (c < U_REM ? c : U_REM);
    const int u1 = u0 + U_BASE + (c < U_REM ? 1 : 0);

    int lt = u0 / KT_PER_TILE, lkt = u0 - lt * KT_PER_TILE;
    int ct = lt, ckt = lkt;

    auto load_stage = [&](int s, int t, int kt) {
        const int m0 = (t >> 3) * BM;
        const int n0 = (t & 7) * BN;
        const char* gA = (const char*)(g_Ah) + ((size_t)m0 * NK) * 2;
        const char* gB = (const char*)(g_Wh) + ((size_t)n0 * NK) * 2;
        const uint32_t dA = sbA + (uint32_t)s * A_TILE;
        const uint32_t dB = sbB + (uint32_t)s * B_TILE;
        const size_t koff = (size_t)kt * BK * 2;
#pragma unroll
        for (int i = 0; i < 16; ++i) {
            int cc = tid + i * 256;
            int row = cc >> 4, col = cc & 15;
            uint32_t doff = (uint32_t)(col >> 3) * A_SUB + ((uint32_t)row << 7)
                          + (((uint32_t)(col & 7) ^ (uint32_t)(row & 7)) << 4);
            cp16(dA + doff, gA + (size_t)row * (NK * 2) + koff + (size_t)col * 16);
        }
#pragma unroll
        for (int i = 0; i < 8; ++i) {
            int cc = tid + i * 256;
            int row = cc >> 4, col = cc & 15;
            uint32_t doff = (uint32_t)(col >> 3) * B_SUB + ((uint32_t)row << 7)
                          + (((uint32_t)(col & 7) ^ (uint32_t)(row & 7)) << 4);
            cp16(dB + doff, gB + (size_t)row * (NK * 2) + koff + (size_t)col * 16);
        }
    };

    load_stage(0, lt, lkt); CP_COMMIT();
    if (++lkt == KT_PER_TILE) { lkt = 0; ++lt; }

    float acc[4][8][4];
#pragma unroll
    for (int mi = 0; mi < 4; ++mi)
#pragma unroll
        for (int ni = 0; ni < 8; ++ni)
#pragma unroll
            for (int r = 0; r < 4; ++r) acc[mi][ni][r] = 0.0f;

    const int arow = wm * 64 + (lane & 15);
    const int brow = wn * 64 + (lane & 7) + ((lane >> 4) << 3);
    const uint32_t aPar  = (uint32_t)(arow & 7);
    const uint32_t bPar  = (uint32_t)(brow & 7);
    const uint32_t aKsel = (uint32_t)(lane >> 4);
    const uint32_t bKsel = (uint32_t)((lane >> 3) & 1);
    const uint32_t aBase = (uint32_t)arow << 7;
    const uint32_t bBase = (uint32_t)brow << 7;

    uint32_t fa[2][4][4];
    uint32_t fb[2][8][2];

    auto load_frags = [&](int buf, uint32_t tAs, uint32_t tBs, int ks) {
        const uint32_t aChunk = (((uint32_t)(ks * 2) + aKsel) ^ aPar) << 4;
#pragma unroll
        for (int mi = 0; mi < 4; ++mi)
            ldmx4(fa[buf][mi][0], fa[buf][mi][1], fa[buf][mi][2], fa[buf][mi][3],
                  tAs + aBase + ((uint32_t)mi << 11) + aChunk);
        const uint32_t bChunk = (((uint32_t)(ks * 2) + bKsel) ^ bPar) << 4;
#pragma unroll
        for (int g = 0; g < 4; ++g) {
            uint32_t q0, q1, q2, q3;
            ldmx4(q0, q1, q2, q3, tBs + bBase + ((uint32_t)g << 11) + bChunk);
            fb[buf][g * 2 + 0][0] = q0; fb[buf][g * 2 + 0][1] = q1;
            fb[buf][g * 2 + 1][0] = q2; fb[buf][g * 2 + 1][1] = q3;
        }
    };
    auto mma_block = [&](int buf) {
#pragma unroll
        for (int mi = 0; mi < 4; ++mi)
#pragma unroll
            for (int ni = 0; ni < 8; ++ni)
                mma16816(acc[mi][ni][0], acc[mi][ni][1], acc[mi][ni][2], acc[mi][ni][3],
                         fa[buf][mi][0], fa[buf][mi][1], fa[buf][mi][2], fa[buf][mi][3],
                         fb[buf][ni][0], fb[buf][ni][1]);
    };

    const int q = lane >> 2, p = lane & 3;
    // dump: full tile -> out; head partial -> g_part[c] + release flag
    auto dump = [&](int t, bool full) {
        if (full) {
            const int m0 = (t >> 3) * BM;
            const int n0 = (t & 7) * BN;
#pragma unroll
            for (int mi = 0; mi < 4; ++mi) {
                int mbase = m0 + wm * 64 + mi * 16 + q;
#pragma unroll
                for (int ni = 0; ni < 8; ++ni) {
                    int nbase = n0 + wn * 64 + ni * 8 + p * 2;
                    *reinterpret_cast<float2*>(out + (size_t)mbase * NOUT + nbase) =
                        make_float2(acc[mi][ni][0], acc[mi][ni][1]);
                    *reinterpret_cast<float2*>(out + (size_t)(mbase + 8) * NOUT + nbase) =
                        make_float2(acc[mi][ni][2], acc[mi][ni][3]);
                }
            }
        } else {
            float* pd = g_part[c];
#pragma unroll
            for (int mi = 0; mi < 4; ++mi) {
                int mrel = wm * 64 + mi * 16 + q;
#pragma unroll
                for (int ni = 0; ni < 8; ++ni) {
                    int nrel = wn * 64 + ni * 8 + p * 2;
                    *reinterpret_cast<float2*>(pd + (size_t)mrel * BN + nrel) =
                        make_float2(acc[mi][ni][0], acc[mi][ni][1]);
                    *reinterpret_cast<float2*>(pd + (size_t)(mrel + 8) * BN + nrel) =
                        make_float2(acc[mi][ni][2], acc[mi][ni][3]);
                }
            }
            __syncthreads();                  // all partial stores done
            if (tid == 0) {
                __threadfence();              // release
                atomicExch(&g_flag[c], 1);
            }
        }
#pragma unroll
        for (int mi = 0; mi < 4; ++mi)
#pragma unroll
            for (int ni = 0; ni < 8; ++ni)
#pragma unroll
                for (int r = 0; r < 4; ++r) acc[mi][ni][r] = 0.0f;
    };

    int s = 0;
    for (int u = u0; u < u1; ++u) {
        CP_WAIT0();
        __syncthreads();

        if (u + 1 < u1) {
            load_stage(s ^ 1, lt, lkt); CP_COMMIT();
            if (++lkt == KT_PER_TILE) { lkt = 0; ++lt; }
        }

        const uint32_t tA = sbA + (uint32_t)s * A_TILE;
        const uint32_t tB = sbB + (uint32_t)s * B_TILE;

        load_frags(0, tA, tB, 0);
#pragma unroll
        for (int k8 = 0; k8 < 8; ++k8) {
            const int nk = k8 + 1;
            if (nk < 8)
                load_frags(nk & 1,
                           tA + (uint32_t)(nk >> 2) * A_SUB,
                           tB + (uint32_t)(nk >> 2) * B_SUB,
                           nk & 3);
            mma_block(k8 & 1);
        }
        s ^= 1;

        if (ckt == KT_PER_TILE - 1)                 // tile complete
            dump(ct, ct * KT_PER_TILE >= u0);       // full unless it's our head partial
        // range_end mid-tile: keep acc in registers for the tail merge below

        if (++ckt == KT_PER_TILE) { ckt = 0; ++ct; }
    }

    // ---- tail merge: our range ended mid-tile; CTA c+1 owns the head partial ----
    if ((u1 % KT_PER_TILE) != 0) {                  // implies c+1 < NCTA (last ends aligned)
        if (tid == 0)
            while (atomicAdd(&g_flag[c + 1], 0) == 0) __nanosleep(64);
        __syncthreads();                            // acquire for all threads
        __threadfence();
        const float* ph = g_part[c + 1];
        const int m0 = (ct >> 3) * BM;
        const int n0 = (ct & 7) * BN;
#pragma unroll
        for (int mi = 0; mi < 4; ++mi) {
            int mrel = wm * 64 + mi * 16 + q;
#pragma unroll
            for (int ni = 0; ni < 8; ++ni) {
                int nrel = wn * 64 + ni * 8 + p * 2;
                float2 h0 = *reinterpret_cast<const float2*>(ph + (size_t)mrel * BN + nrel);
                float2 h1 = *reinterpret_cast<const float2*>(ph + (size_t)(mrel + 8) * BN + nrel);
                *reinterpret_cast<float2*>(out + (size_t)(m0 + mrel) * NOUT + n0 + nrel) =
                    make_float2(acc[mi][ni][0] + h0.x, acc[mi][ni][1] + h0.y);
                *reinterpret_cast<float2*>(out + (size_t)(m0 + mrel + 8) * NOUT + n0 + nrel) =
                    make_float2(acc[mi][ni][2] + h1.x, acc[mi][ni][3] + h1.y);
            }
        }
    }
}

// ===================== host launcher =====================
extern "C" void kernel_launch(void* const* d_in, const int* in_sizes, int n_in,
                              void* d_out, int out_size) {
    const float* x  = (const float*)d_in[0];
    const float* bw = (const float*)d_in[1];
    const float* sw = (const float*)d_in[2];
    float* out = (float*)d_out;

    cudaFuncSetAttribute(kan_gemm, cudaFuncAttributeMaxDynamicSharedMemorySize,
                         (int)SMEM_TOTAL);

    kan_prep<<<WPACK_BLOCKS + ACT_BLOCKS, 256>>>(x, bw, sw);
    kan_gemm<<<NCTA, 256, SMEM_TOTAL>>>(out);
}